// round 14
// baseline (speedup 1.0000x reference)
#include <cuda_runtime.h>
#include <cuda.h>
#include <cstdint>

#define BB 8
#define SS 1024
#define HH 128

// ---------------- scratch ----------------
__device__ float g_scores[(size_t)BB * SS * SS];        // e = exp(score)
__device__ float g_part[(size_t)BB * SS * 32];          // per-jblock partial row sums
__device__ float g_denom[(size_t)BB * SS];              // row denominators
__device__ float g_xT[(size_t)BB * HH * SS];            // x transposed: [b][h][j]

// ---------------- helpers ----------------
__device__ __forceinline__ void ffma2(unsigned long long &acc, unsigned long long a, unsigned long long b) {
    asm("fma.rn.f32x2 %0, %1, %2, %0;" : "+l"(acc) : "l"(a), "l"(b));
}
__device__ __forceinline__ void unpack2(unsigned long long p, float &lo, float &hi) {
    asm("mov.b64 {%0, %1}, %2;" : "=f"(lo), "=f"(hi) : "l"(p));
}
__device__ __forceinline__ void cpa16(uint32_t s, const void* g) {
    asm volatile("cp.async.cg.shared.global [%0], [%1], 16;" :: "r"(s), "l"(g));
}
#define CP_COMMIT() asm volatile("cp.async.commit_group;" ::: "memory")
#define CP_WAIT2()  asm volatile("cp.async.wait_group 2;" ::: "memory")

#define MBARRIER_INIT(a, n) \
    asm volatile("mbarrier.init.shared.b64 [%0], %1;" :: "r"(a), "r"(n) : "memory")
#define MBARRIER_EXPECT_TX(a, tx) \
    asm volatile("mbarrier.arrive.expect_tx.shared.b64 _, [%0], %1;" :: "r"(a), "r"(tx) : "memory")
#define MBARRIER_ARRIVE(a) \
    asm volatile("mbarrier.arrive.release.cta.shared.b64 _, [%0];" :: "r"(a) : "memory")
#define MBARRIER_WAIT(a, ph) do { \
    asm volatile("{\n\t.reg .pred P;\n\tWL%=:\n\t" \
        "mbarrier.try_wait.parity.acquire.cta.shared::cta.b64 P, [%0], %1, 0x989680;\n\t" \
        "@P bra.uni WD%=;\n\tbra.uni WL%=;\n\tWD%=:\n\t}" \
        :: "r"(a), "r"(ph) : "memory"); \
} while (0)
#define TMA_LOAD_3D(smem_addr, map, cx, cy, cz, mbar) \
    asm volatile("cp.async.bulk.tensor.3d.shared::cta.global.tile.mbarrier::complete_tx::bytes " \
        "[%0], [%1, {%2, %3, %4}], [%5];" \
        :: "r"((uint32_t)(smem_addr)), "l"(map), "r"((int)(cx)), "r"((int)(cy)), "r"((int)(cz)), \
           "r"((uint32_t)(mbar)) : "memory")

// =====================================================================
// Kernel A (measured 107.8us, unchanged): e[b,i,j] = exp(sum_h x*rel)
// + per-jblock row sums. 256 thr = 32 j x 4 ig x 2 h-halves.
// TMA 5-stage, rotating producer warp.
// =====================================================================
#define TIA 32
#define TJA 32
#define HCA 8
#define NCHA (HH / HCA)         // 16
#define NSTAGE 5
#define REL_BYTES (TIA * TJA * HCA * 4)   // 32768
#define X_BYTES   (BB * TJA * HCA * 4)    // 8192
#define STAGE_BYTES (REL_BYTES + X_BYTES) // 40960
#define SMEMA (1024 + NSTAGE * STAGE_BYTES)

__global__ void __launch_bounds__(256, 1)
scores_kernel(const __grid_constant__ CUtensorMap tmr,
              const __grid_constant__ CUtensorMap tmx,
              float* __restrict__ scores,
              float* __restrict__ part) {
    extern __shared__ __align__(1024) char sm[];
    const uint32_t sbase = (uint32_t)__cvta_generic_to_shared(sm);
    const uint32_t mb = sbase;
    const int t  = threadIdx.x;
    const int j  = t & 31;
    const int g  = t >> 5;
    const int hg = g >> 2;
    const int ig = g & 3;
    const int i0 = blockIdx.y * TIA;
    const int j0 = blockIdx.x * TJA;
    const int fo = (16 * hg) ^ (((j >> 2) & 1) << 4);

    if (t == 0) {
#pragma unroll
        for (int s = 0; s < NSTAGE; s++) {
            MBARRIER_INIT(mb + s * 16, 1);
            MBARRIER_INIT(mb + s * 16 + 8, 256);
        }
    }
    __syncthreads();

    if (t == 0) {
#pragma unroll
        for (int n = 0; n < NSTAGE; n++) {
            uint32_t fb = mb + n * 16;
            uint32_t dst = sbase + 1024 + n * STAGE_BYTES;
            MBARRIER_EXPECT_TX(fb, STAGE_BYTES);
            TMA_LOAD_3D(dst, &tmr, n * HCA, j0, i0, fb);
            TMA_LOAD_3D(dst + REL_BYTES, &tmx, n * HCA, j0, 0, fb);
        }
    }

    unsigned long long acc[8][8] = {};

    for (int c = 0; c < NCHA; c++) {
        const int slot = c % NSTAGE;
        const int ph = (c / NSTAGE) & 1;
        MBARRIER_WAIT(mb + slot * 16, ph);

        const char* st = sm + 1024 + slot * STAGE_BYTES;
        const char* rb = st + ((ig * 8) * TJA + j) * 32 + fo;
        const char* xb = st + REL_BYTES + (size_t)j * 32 + fo;

        ulonglong2 xv[8], rv[8];
#pragma unroll
        for (int q = 0; q < 8; q++)
            xv[q] = *(const ulonglong2*)(xb + q * (TJA * 32));
#pragma unroll
        for (int p = 0; p < 8; p++)
            rv[p] = *(const ulonglong2*)(rb + p * (TJA * 32));

        MBARRIER_ARRIVE(mb + slot * 16 + 8);

        if (g == (c & 7) && c + NSTAGE < NCHA) {
            const int n = c + NSTAGE;
            const int eph = ((n / NSTAGE) + 1) & 1;
            MBARRIER_WAIT(mb + slot * 16 + 8, eph);
            if (j == 0) {
                uint32_t fb = mb + slot * 16;
                uint32_t dst = sbase + 1024 + slot * STAGE_BYTES;
                MBARRIER_EXPECT_TX(fb, STAGE_BYTES);
                TMA_LOAD_3D(dst, &tmr, n * HCA, j0, i0, fb);
                TMA_LOAD_3D(dst + REL_BYTES, &tmx, n * HCA, j0, 0, fb);
            }
        }

#pragma unroll
        for (int p = 0; p < 8; p++)
#pragma unroll
            for (int q = 0; q < 8; q++) {
                ffma2(acc[p][q], rv[p].x, xv[q].x);
                ffma2(acc[p][q], rv[p].y, xv[q].y);
            }
    }

    __syncthreads();
    float* red = (float*)(sm + 1024);
    if (hg == 1) {
#pragma unroll
        for (int p = 0; p < 8; p++)
#pragma unroll
            for (int q = 0; q < 8; q++) {
                float lo, hi; unpack2(acc[p][q], lo, hi);
                red[(((ig * 8 + p) * 8) + q) * 32 + j] = lo + hi;
            }
    }
    __syncthreads();
    if (hg == 0) {
#pragma unroll
        for (int p = 0; p < 8; p++) {
            const int i = i0 + ig * 8 + p;
#pragma unroll
            for (int q = 0; q < 8; q++) {
                float lo, hi; unpack2(acc[p][q], lo, hi);
                float v = lo + hi + red[(((ig * 8 + p) * 8) + q) * 32 + j];
                float e = __expf(v);   // no max-subtract: |score| small, f32-safe
                scores[((size_t)q * SS + i) * SS + j0 + j] = e;
                float s = e;
#pragma unroll
                for (int o = 16; o > 0; o >>= 1) s += __shfl_xor_sync(0xffffffffu, s, o);
                if (j == 0)
                    part[(((size_t)q * SS + i) << 5) + blockIdx.x] = s;
            }
        }
    }
}

// ---------------- reduce: denom[r] = sum of 32 partials ----------------
__global__ void reduce_kernel(const float* __restrict__ part, float* __restrict__ denom) {
    const int r = blockIdx.x * 256 + threadIdx.x;
    const float* p = part + ((size_t)r << 5);
    float s = 0.f;
#pragma unroll
    for (int k = 0; k < 32; k++) s += p[k];
    denom[r] = s;
}

// ---------------- xT[b][h][j] = x[b][j][h] (measured 5.2us) ----------------
__global__ void xT_kernel(const float* __restrict__ x, float* __restrict__ xT) {
    __shared__ float tile[32][33];
    const int b = blockIdx.z;
    const int j0 = blockIdx.x * 32, h0 = blockIdx.y * 32;
    const int tx = threadIdx.x, ty = threadIdx.y;
#pragma unroll
    for (int k = 0; k < 4; k++)
        tile[ty + k * 8][tx] = x[((size_t)b * SS + j0 + ty + k * 8) * HH + h0 + tx];
    __syncthreads();
#pragma unroll
    for (int k = 0; k < 4; k++)
        xT[((size_t)b * HH + h0 + ty + k * 8) * SS + j0 + tx] = tile[tx][ty + k * 8];
}

// =====================================================================
// Kernel B v6: out[b,i,h] = (sum_j e[b,i,j]*x[b,j,h]) / denom[b,i]
// 512 thr (16 warps/SM -> 4/SMSP for latency hiding), MTB=64,
// grid 16x8 = 128 CTAs (one wave). tx=h-quad(32), ty=i-group of 4.
// j-contiguous operands + quad-rotation swizzle (conflict-free).
// 4-stage cp.async ring, lookahead 3.
// =====================================================================
#define MTB 64
#define KTB 32
#define NCHB (SS / KTB)
#define WROW 36
#define XROW 32
#define WF (MTB * WROW)       // 2304 floats
#define XFB (HH * XROW)       // 4096 floats
#define BUFBF (WF + XFB)      // 6400 floats = 25600 B
#define NBUFB 4               // 102400 B

__global__ void __launch_bounds__(512, 1)
out_kernel(const float* __restrict__ w,
           const float* __restrict__ xT,
           const float* __restrict__ denom,
           float* __restrict__ out) {
    extern __shared__ float smB[];
    const int t  = threadIdx.x;
    const int tx = t & 31;       // h-quad: xT rows tx*4..+3
    const int ty = t >> 5;       // i-group of 4 (0..15)
    const int b  = blockIdx.y;
    const int m0 = blockIdx.x * MTB;
    const float* wb = w + (size_t)b * SS * SS;
    const float* xb = xT + (size_t)b * HH * SS;
    const uint32_t sbase = (uint32_t)__cvta_generic_to_shared(smB);

    auto stage = [&](int c, int s) {
        uint32_t bbase = sbase + (uint32_t)s * (BUFBF * 4);
        // w: 64 i-rows x 8 float4 (32 j) = 512 f4 -> 1 per thread
        {
            int f4 = t & 7, row = t >> 3;
            cpa16(bbase + (uint32_t)(row * WROW + f4 * 4) * 4,
                  wb + (size_t)(m0 + row) * SS + c * KTB + f4 * 4);
        }
        // xT: 128 h-rows x 8 float4 (32 j), quad-rotated by (row>>2) -> 2 per thread
#pragma unroll
        for (int k = 0; k < 2; k++) {
            int idx = t + k * 512;
            int f4 = idx & 7, row = idx >> 3;
            int qs = (f4 + (row >> 2)) & 7;
            cpa16(bbase + (uint32_t)(WF + row * XROW + qs * 4) * 4,
                  xb + (size_t)row * SS + c * KTB + f4 * 4);
        }
    };

    stage(0, 0); CP_COMMIT();
    stage(1, 1); CP_COMMIT();
    stage(2, 2); CP_COMMIT();

    unsigned long long acc2[4][4] = {};   // (even-j, odd-j) per (i, h)

    int buf = 0;
    for (int c = 0; c < NCHB; c++) {
        CP_WAIT2();
        __syncthreads();
        if (c + 3 < NCHB) {
            int nb = buf + 3; if (nb >= NBUFB) nb -= NBUFB;
            stage(c + 3, nb);
        }
        CP_COMMIT();

        const float* wsb = smB + (size_t)buf * BUFBF;
        const float* xsb = wsb + WF;
#pragma unroll
        for (int j4 = 0; j4 < KTB / 4; j4++) {
            const int qs = ((j4 + tx) & 7) * 4;   // rotated quad for rows tx*4..+3
            ulonglong2 xq[4];
#pragma unroll
            for (int h = 0; h < 4; h++)
                xq[h] = *reinterpret_cast<const ulonglong2*>(xsb + (tx * 4 + h) * XROW + qs);
#pragma unroll
            for (int p = 0; p < 4; p++) {
                ulonglong2 wv = *reinterpret_cast<const ulonglong2*>(wsb + (ty * 4 + p) * WROW + j4 * 4);
#pragma unroll
                for (int h = 0; h < 4; h++) {
                    ffma2(acc2[p][h], wv.x, xq[h].x);
                    ffma2(acc2[p][h], wv.y, xq[h].y);
                }
            }
        }
        buf++; if (buf == NBUFB) buf = 0;
    }

#pragma unroll
    for (int p = 0; p < 4; p++) {
        float inv = 1.0f / denom[(size_t)b * SS + m0 + ty * 4 + p];
        float4 o;
        {
            float lo, hi;
            unpack2(acc2[p][0], lo, hi); o.x = (lo + hi) * inv;
            unpack2(acc2[p][1], lo, hi); o.y = (lo + hi) * inv;
            unpack2(acc2[p][2], lo, hi); o.z = (lo + hi) * inv;
            unpack2(acc2[p][3], lo, hi); o.w = (lo + hi) * inv;
        }
        *reinterpret_cast<float4*>(out + ((size_t)b * SS + m0 + ty * 4 + p) * HH + tx * 4) = o;
    }
}

// ---------------- launch ----------------
typedef CUresult (*EncodeFn)(CUtensorMap*, CUtensorMapDataType, cuuint32_t, void*,
                             const cuuint64_t*, const cuuint64_t*, const cuuint32_t*,
                             const cuuint32_t*, CUtensorMapInterleave, CUtensorMapSwizzle,
                             CUtensorMapL2promotion, CUtensorMapFloatOOBfill);

extern "C" void kernel_launch(void* const* d_in, const int* in_sizes, int n_in,
                              void* d_out, int out_size) {
    const float* x   = (const float*)d_in[0];   // (8, 1024, 128) f32
    const float* rel = (const float*)d_in[1];   // (1024, 1024, 128) f32
    float* out = (float*)d_out;

    float *scores = nullptr, *part = nullptr, *denom = nullptr, *xT = nullptr;
    cudaGetSymbolAddress((void**)&scores, g_scores);
    cudaGetSymbolAddress((void**)&part, g_part);
    cudaGetSymbolAddress((void**)&denom, g_denom);
    cudaGetSymbolAddress((void**)&xT, g_xT);

    EncodeFn enc = nullptr;
    cudaDriverEntryPointQueryResult qr;
    cudaGetDriverEntryPoint("cuTensorMapEncodeTiled", (void**)&enc, cudaEnableDefault, &qr);

    CUtensorMap tmr, tmx;
    {
        cuuint64_t dims[3]    = {HH, SS, SS};
        cuuint64_t strides[2] = {HH * 4ull, (cuuint64_t)SS * HH * 4ull};
        cuuint32_t box[3]     = {HCA, TJA, TIA};
        cuuint32_t es[3]      = {1, 1, 1};
        enc(&tmr, CU_TENSOR_MAP_DATA_TYPE_FLOAT32, 3, (void*)rel, dims, strides, box, es,
            CU_TENSOR_MAP_INTERLEAVE_NONE, CU_TENSOR_MAP_SWIZZLE_32B,
            CU_TENSOR_MAP_L2_PROMOTION_L2_128B, CU_TENSOR_MAP_FLOAT_OOB_FILL_NONE);
    }
    {
        cuuint64_t dims[3]    = {HH, SS, BB};
        cuuint64_t strides[2] = {HH * 4ull, (cuuint64_t)SS * HH * 4ull};
        cuuint32_t box[3]     = {HCA, TJA, BB};
        cuuint32_t es[3]      = {1, 1, 1};
        enc(&tmx, CU_TENSOR_MAP_DATA_TYPE_FLOAT32, 3, (void*)x, dims, strides, box, es,
            CU_TENSOR_MAP_INTERLEAVE_NONE, CU_TENSOR_MAP_SWIZZLE_32B,
            CU_TENSOR_MAP_L2_PROMOTION_L2_128B, CU_TENSOR_MAP_FLOAT_OOB_FILL_NONE);
    }

    xT_kernel<<<dim3(SS / 32, HH / 32, BB), dim3(32, 8)>>>(x, xT);

    cudaFuncSetAttribute(scores_kernel, cudaFuncAttributeMaxDynamicSharedMemorySize, SMEMA);
    scores_kernel<<<dim3(SS / TJA, SS / TIA), 256, SMEMA>>>(tmr, tmx, scores, part);

    reduce_kernel<<<BB * SS / 256, 256>>>(part, denom);

    const int smB_bytes = NBUFB * BUFBF * 4;    // 102400
    cudaFuncSetAttribute(out_kernel, cudaFuncAttributeMaxDynamicSharedMemorySize, smB_bytes);
    out_kernel<<<dim3(SS / MTB, BB), 512, smB_bytes>>>(scores, xT, denom, out);
}

// round 17
// speedup vs baseline: 1.0366x; 1.0366x over previous
#include <cuda_runtime.h>
#include <cuda.h>
#include <cstdint>

#define BB 8
#define SS 1024
#define HH 128

// ---------------- scratch ----------------
__device__ float g_scores[(size_t)BB * SS * SS];        // e = exp(score)
__device__ float g_part[(size_t)BB * SS * 32];          // per-jblock partial row sums

// ---------------- helpers ----------------
__device__ __forceinline__ void ffma2(unsigned long long &acc, unsigned long long a, unsigned long long b) {
    asm("fma.rn.f32x2 %0, %1, %2, %0;" : "+l"(acc) : "l"(a), "l"(b));
}
__device__ __forceinline__ void unpack2(unsigned long long p, float &lo, float &hi) {
    asm("mov.b64 {%0, %1}, %2;" : "=f"(lo), "=f"(hi) : "l"(p));
}
__device__ __forceinline__ void cpa16(uint32_t s, const void* g) {
    asm volatile("cp.async.cg.shared.global [%0], [%1], 16;" :: "r"(s), "l"(g));
}
#define CP_COMMIT() asm volatile("cp.async.commit_group;" ::: "memory")
#define CP_WAIT2()  asm volatile("cp.async.wait_group 2;" ::: "memory")

#define MBARRIER_INIT(a, n) \
    asm volatile("mbarrier.init.shared.b64 [%0], %1;" :: "r"(a), "r"(n) : "memory")
#define MBARRIER_EXPECT_TX(a, tx) \
    asm volatile("mbarrier.arrive.expect_tx.shared.b64 _, [%0], %1;" :: "r"(a), "r"(tx) : "memory")
#define MBARRIER_ARRIVE(a) \
    asm volatile("mbarrier.arrive.release.cta.shared.b64 _, [%0];" :: "r"(a) : "memory")
#define MBARRIER_WAIT(a, ph) do { \
    asm volatile("{\n\t.reg .pred P;\n\tWL%=:\n\t" \
        "mbarrier.try_wait.parity.acquire.cta.shared::cta.b64 P, [%0], %1, 0x989680;\n\t" \
        "@P bra.uni WD%=;\n\tbra.uni WL%=;\n\tWD%=:\n\t}" \
        :: "r"(a), "r"(ph) : "memory"); \
} while (0)
#define TMA_LOAD_3D(smem_addr, map, cx, cy, cz, mbar) \
    asm volatile("cp.async.bulk.tensor.3d.shared::cta.global.tile.mbarrier::complete_tx::bytes " \
        "[%0], [%1, {%2, %3, %4}], [%5];" \
        :: "r"((uint32_t)(smem_addr)), "l"(map), "r"((int)(cx)), "r"((int)(cy)), "r"((int)(cz)), \
           "r"((uint32_t)(mbar)) : "memory")

// =====================================================================
// Kernel A (measured 107.8us, unchanged): e[b,i,j] = exp(sum_h x*rel)
// + per-jblock row sums. 256 thr = 32 j x 4 ig x 2 h-halves.
// TMA 5-stage, rotating producer warp.
// =====================================================================
#define TIA 32
#define TJA 32
#define HCA 8
#define NCHA (HH / HCA)         // 16
#define NSTAGE 5
#define REL_BYTES (TIA * TJA * HCA * 4)   // 32768
#define X_BYTES   (BB * TJA * HCA * 4)    // 8192
#define STAGE_BYTES (REL_BYTES + X_BYTES) // 40960
#define SMEMA (1024 + NSTAGE * STAGE_BYTES)

__global__ void __launch_bounds__(256, 1)
scores_kernel(const __grid_constant__ CUtensorMap tmr,
              const __grid_constant__ CUtensorMap tmx,
              float* __restrict__ scores,
              float* __restrict__ part) {
    extern __shared__ __align__(1024) char sm[];
    const uint32_t sbase = (uint32_t)__cvta_generic_to_shared(sm);
    const uint32_t mb = sbase;
    const int t  = threadIdx.x;
    const int j  = t & 31;
    const int g  = t >> 5;
    const int hg = g >> 2;
    const int ig = g & 3;
    const int i0 = blockIdx.y * TIA;
    const int j0 = blockIdx.x * TJA;
    const int fo = (16 * hg) ^ (((j >> 2) & 1) << 4);

    if (t == 0) {
#pragma unroll
        for (int s = 0; s < NSTAGE; s++) {
            MBARRIER_INIT(mb + s * 16, 1);
            MBARRIER_INIT(mb + s * 16 + 8, 256);
        }
    }
    __syncthreads();

    if (t == 0) {
#pragma unroll
        for (int n = 0; n < NSTAGE; n++) {
            uint32_t fb = mb + n * 16;
            uint32_t dst = sbase + 1024 + n * STAGE_BYTES;
            MBARRIER_EXPECT_TX(fb, STAGE_BYTES);
            TMA_LOAD_3D(dst, &tmr, n * HCA, j0, i0, fb);
            TMA_LOAD_3D(dst + REL_BYTES, &tmx, n * HCA, j0, 0, fb);
        }
    }

    unsigned long long acc[8][8] = {};

    for (int c = 0; c < NCHA; c++) {
        const int slot = c % NSTAGE;
        const int ph = (c / NSTAGE) & 1;
        MBARRIER_WAIT(mb + slot * 16, ph);

        const char* st = sm + 1024 + slot * STAGE_BYTES;
        const char* rb = st + ((ig * 8) * TJA + j) * 32 + fo;
        const char* xb = st + REL_BYTES + (size_t)j * 32 + fo;

        ulonglong2 xv[8], rv[8];
#pragma unroll
        for (int q = 0; q < 8; q++)
            xv[q] = *(const ulonglong2*)(xb + q * (TJA * 32));
#pragma unroll
        for (int p = 0; p < 8; p++)
            rv[p] = *(const ulonglong2*)(rb + p * (TJA * 32));

        MBARRIER_ARRIVE(mb + slot * 16 + 8);

        if (g == (c & 7) && c + NSTAGE < NCHA) {
            const int n = c + NSTAGE;
            const int eph = ((n / NSTAGE) + 1) & 1;
            MBARRIER_WAIT(mb + slot * 16 + 8, eph);
            if (j == 0) {
                uint32_t fb = mb + slot * 16;
                uint32_t dst = sbase + 1024 + slot * STAGE_BYTES;
                MBARRIER_EXPECT_TX(fb, STAGE_BYTES);
                TMA_LOAD_3D(dst, &tmr, n * HCA, j0, i0, fb);
                TMA_LOAD_3D(dst + REL_BYTES, &tmx, n * HCA, j0, 0, fb);
            }
        }

#pragma unroll
        for (int p = 0; p < 8; p++)
#pragma unroll
            for (int q = 0; q < 8; q++) {
                ffma2(acc[p][q], rv[p].x, xv[q].x);
                ffma2(acc[p][q], rv[p].y, xv[q].y);
            }
    }

    __syncthreads();
    float* red = (float*)(sm + 1024);
    if (hg == 1) {
#pragma unroll
        for (int p = 0; p < 8; p++)
#pragma unroll
            for (int q = 0; q < 8; q++) {
                float lo, hi; unpack2(acc[p][q], lo, hi);
                red[(((ig * 8 + p) * 8) + q) * 32 + j] = lo + hi;
            }
    }
    __syncthreads();
    if (hg == 0) {
#pragma unroll
        for (int p = 0; p < 8; p++) {
            const int i = i0 + ig * 8 + p;
#pragma unroll
            for (int q = 0; q < 8; q++) {
                float lo, hi; unpack2(acc[p][q], lo, hi);
                float v = lo + hi + red[(((ig * 8 + p) * 8) + q) * 32 + j];
                float e = __expf(v);   // no max-subtract: |score| small, f32-safe
                scores[((size_t)q * SS + i) * SS + j0 + j] = e;
                float s = e;
#pragma unroll
                for (int o = 16; o > 0; o >>= 1) s += __shfl_xor_sync(0xffffffffu, s, o);
                if (j == 0)
                    part[(((size_t)q * SS + i) << 5) + blockIdx.x] = s;
            }
        }
    }
}

// =====================================================================
// Kernel B v7: out[b,i,h] = (sum_j e[b,i,j]*x[b,j,h]) / denom[b,i]
// 512 thr = 32 tx (h-quads) x 8 ty (i-groups of 8) x 2 j-halves.
// Per-warp LDS halves vs 256-thr version; TOTAL LDS identical ->
// 4 warps/SMSP latency hiding with no crossbar cost.
// x staged from gmem with inline register transpose into the
// quad-rotation-swizzled layout (banks verified all-distinct).
// Denominator computed in prologue from part[] (reduce kernel gone).
// w on 4-deep cp.async ring; x on 2-deep reg->smem double buffer.
// =====================================================================
#define MTB 64
#define KTB 32
#define NCHB (SS / KTB)       // 32
#define WROW 36
#define WF (MTB * WROW)       // 2304 floats per w buffer
#define XSF (HH * 32)         // 4096 floats per x buffer
#define XS_OFF (4 * WF)       // 9216
#define DEN_OFF (XS_OFF + 2 * XSF)   // 17408
#define SMB_BYTES ((DEN_OFF + 64) * 4)  // 69888

__global__ void __launch_bounds__(512, 1)
out_kernel(const float* __restrict__ w,
           const float* __restrict__ x,
           const float* __restrict__ part,
           float* __restrict__ out) {
    extern __shared__ float smB[];
    const int t  = threadIdx.x;
    const int tx = t & 31;        // h-quad
    const int tg = t >> 5;        // warp 0..15
    const int ty = tg & 7;        // i-group of 8
    const int jh = tg >> 3;       // j-half (j4 parity)
    const int b  = blockIdx.y;
    const int m0 = blockIdx.x * MTB;
    const float* wb = w + (size_t)b * SS * SS;
    const float* xg = x + (size_t)b * SS * HH;
    const uint32_t sbase = (uint32_t)__cvta_generic_to_shared(smB);

    // x staging decomposition: warp wp, lane l: hq=l&7, jj=(l>>3)&3
    const int hq_s = t & 7;
    const int jj_s = (t >> 3) & 3;
    const int j_s  = (tg & 7) * 4 + jj_s;   // local j 0..31
    const int seg  = tg >> 3;               // h segment 0..1

    auto stage_w = [&](int c, int s) {
        uint32_t bb = sbase + (uint32_t)s * (WF * 4);
        int f4 = t & 7, row = t >> 3;       // 512 threads = 512 float4
        cpa16(bb + (uint32_t)(row * WROW + f4 * 4) * 4,
              wb + (size_t)(m0 + row) * SS + c * KTB + f4 * 4);
    };
    auto ldg_x = [&](int c, float4* rx) {
#pragma unroll
        for (int k = 0; k < 2; k++) {
            int h0 = ((seg * 2 + k) * 8 + hq_s) * 4;
            rx[k] = *(const float4*)(xg + (size_t)(c * KTB + j_s) * HH + h0);
        }
    };
    auto sts_x = [&](int c, const float4* rx) {
        float* xs = smB + XS_OFF + (c & 1) * XSF;
#pragma unroll
        for (int k = 0; k < 2; k++) {
            int h0 = ((seg * 2 + k) * 8 + hq_s) * 4;
            const float* v = (const float*)&rx[k];
#pragma unroll
            for (int f = 0; f < 4; f++) {
                int h = h0 + f;
                int pj = ((((j_s >> 2) + (h >> 2)) & 7) << 2) + (j_s & 3);
                xs[h * 32 + pj] = v[f];
            }
        }
    };

    // prologue
    float4 rx[2];
    ldg_x(0, rx);
    stage_w(0, 0); CP_COMMIT();
    stage_w(1, 1); CP_COMMIT();
    stage_w(2, 2); CP_COMMIT();
    // fused denominator: rows m0..m0+63 from part
    if (t < 64) {
        float s = 0.f;
        const float* pp = part + ((size_t)(b * SS + m0 + t) << 5);
#pragma unroll
        for (int k2 = 0; k2 < 32; k2++) s += pp[k2];
        smB[DEN_OFF + t] = s;
    }
    sts_x(0, rx);
    ldg_x(1, rx);

    unsigned long long acc2[8][4] = {};   // (even-j, odd-j) per (i, h)

    for (int c = 0; c < NCHB; c++) {
        CP_WAIT2();
        __syncthreads();

        const float* wsb = smB + (c & 3) * WF;
        const float* xsb = smB + XS_OFF + (c & 1) * XSF;
#pragma unroll
        for (int k = 0; k < 4; k++) {
            const int j4 = jh + k * 2;            // this warp's 4 of 8 j4's
            const int qs = ((j4 + tx) & 7) * 4;   // rotated quad
            ulonglong2 xq[4];
#pragma unroll
            for (int h = 0; h < 4; h++)
                xq[h] = *(const ulonglong2*)(xsb + (tx * 4 + h) * 32 + qs);
#pragma unroll
            for (int p = 0; p < 8; p++) {
                ulonglong2 wv = *(const ulonglong2*)(wsb + (ty * 8 + p) * WROW + j4 * 4);
#pragma unroll
                for (int h = 0; h < 4; h++) {
                    ffma2(acc2[p][h], wv.x, xq[h].x);
                    ffma2(acc2[p][h], wv.y, xq[h].y);
                }
            }
        }

        if (c + 3 < NCHB) stage_w(c + 3, (c + 3) & 3);
        CP_COMMIT();
        if (c + 1 < NCHB) {
            sts_x(c + 1, rx);
            if (c + 2 < NCHB) ldg_x(c + 2, rx);
        }
    }

    // epilogue: combine j-halves via smem (reuse w ring area, 64KB)
    __syncthreads();
    unsigned long long* scr = (unsigned long long*)smB;
    if (jh == 1) {
#pragma unroll
        for (int p = 0; p < 8; p++)
#pragma unroll
            for (int h = 0; h < 4; h++)
                scr[(p * 4 + h) * 256 + ty * 32 + tx] = acc2[p][h];
    }
    __syncthreads();
    if (jh == 0) {
#pragma unroll
        for (int p = 0; p < 8; p++) {
            float inv = 1.0f / smB[DEN_OFF + ty * 8 + p];
            float o[4];
#pragma unroll
            for (int h = 0; h < 4; h++) {
                float alo, ahi, blo, bhi;
                unpack2(acc2[p][h], alo, ahi);
                unpack2(scr[(p * 4 + h) * 256 + ty * 32 + tx], blo, bhi);
                o[h] = ((alo + ahi) + (blo + bhi)) * inv;
            }
            float4 ov = make_float4(o[0], o[1], o[2], o[3]);
            *reinterpret_cast<float4*>(out + ((size_t)b * SS + m0 + ty * 8 + p) * HH + tx * 4) = ov;
        }
    }
}

// ---------------- launch ----------------
typedef CUresult (*EncodeFn)(CUtensorMap*, CUtensorMapDataType, cuuint32_t, void*,
                             const cuuint64_t*, const cuuint64_t*, const cuuint32_t*,
                             const cuuint32_t*, CUtensorMapInterleave, CUtensorMapSwizzle,
                             CUtensorMapL2promotion, CUtensorMapFloatOOBfill);

extern "C" void kernel_launch(void* const* d_in, const int* in_sizes, int n_in,
                              void* d_out, int out_size) {
    const float* x   = (const float*)d_in[0];   // (8, 1024, 128) f32
    const float* rel = (const float*)d_in[1];   // (1024, 1024, 128) f32
    float* out = (float*)d_out;

    float *scores = nullptr, *part = nullptr;
    cudaGetSymbolAddress((void**)&scores, g_scores);
    cudaGetSymbolAddress((void**)&part, g_part);

    EncodeFn enc = nullptr;
    cudaDriverEntryPointQueryResult qr;
    cudaGetDriverEntryPoint("cuTensorMapEncodeTiled", (void**)&enc, cudaEnableDefault, &qr);

    CUtensorMap tmr, tmx;
    {
        cuuint64_t dims[3]    = {HH, SS, SS};
        cuuint64_t strides[2] = {HH * 4ull, (cuuint64_t)SS * HH * 4ull};
        cuuint32_t box[3]     = {HCA, TJA, TIA};
        cuuint32_t es[3]      = {1, 1, 1};
        enc(&tmr, CU_TENSOR_MAP_DATA_TYPE_FLOAT32, 3, (void*)rel, dims, strides, box, es,
            CU_TENSOR_MAP_INTERLEAVE_NONE, CU_TENSOR_MAP_SWIZZLE_32B,
            CU_TENSOR_MAP_L2_PROMOTION_L2_128B, CU_TENSOR_MAP_FLOAT_OOB_FILL_NONE);
    }
    {
        cuuint64_t dims[3]    = {HH, SS, BB};
        cuuint64_t strides[2] = {HH * 4ull, (cuuint64_t)SS * HH * 4ull};
        cuuint32_t box[3]     = {HCA, TJA, BB};
        cuuint32_t es[3]      = {1, 1, 1};
        enc(&tmx, CU_TENSOR_MAP_DATA_TYPE_FLOAT32, 3, (void*)x, dims, strides, box, es,
            CU_TENSOR_MAP_INTERLEAVE_NONE, CU_TENSOR_MAP_SWIZZLE_32B,
            CU_TENSOR_MAP_L2_PROMOTION_L2_128B, CU_TENSOR_MAP_FLOAT_OOB_FILL_NONE);
    }

    cudaFuncSetAttribute(scores_kernel, cudaFuncAttributeMaxDynamicSharedMemorySize, SMEMA);
    scores_kernel<<<dim3(SS / TJA, SS / TIA), 256, SMEMA>>>(tmr, tmx, scores, part);

    cudaFuncSetAttribute(out_kernel, cudaFuncAttributeMaxDynamicSharedMemorySize, SMB_BYTES);
    out_kernel<<<dim3(SS / MTB, BB), 512, SMB_BYTES>>>(scores, x, part, out);
}